// round 5
// baseline (speedup 1.0000x reference)
#include <cuda_runtime.h>
#include <cstdint>

#define NW 14
#define NSTATE (1 << NW)        // 16384 amplitudes
#define NLAYERS 6               // (DEPTH+1) * SEL_LAYERS
#define NTHREADS 512
#define NPARAMS (2 * NW * 3)    // 84

// ---------------------------------------------------------------------------
// Compile-time GF(2) algebra: lazy CNOT permutation tracking.
// Storage invariant: psi[x] = a[T * x] (T invertible 14x14 over GF(2)).
// Rot on wire w pairs physical (j, j^v), v = col_w(T); role parity =
// <row_w(Tinv), j>.  Linear swizzle sw(j)=j^(j>>4)^(j>>9) folded into offsets.
// ---------------------------------------------------------------------------

struct GroupTab {
    int      piv[4];     // sorted pivot bit positions for coset enumeration
    uint16_t offs[16];   // PRE-SWIZZLED xor-offsets of the 2^g coset members
    uint16_t umask[4];   // role-parity masks (rows of Tinv)
    uint8_t  uidx[4];    // index into U-matrix table: l*NW + w
};
struct Tables {
    GroupTab grp[NLAYERS][4];
    uint16_t zu[NW];     // final Tinv rows -> measurement sign masks
};

__host__ __device__ constexpr unsigned swz(unsigned j) {
    return j ^ (j >> 4) ^ (j >> 9);
}

constexpr Tables build_tables() {
    Tables t{};
    const int GSIZE[4]  = {4, 4, 3, 3};
    const int GSTART[4] = {0, 4, 8, 11};
    uint16_t Tcol[NW]  = {};
    uint16_t TiRow[NW] = {};
    for (int i = 0; i < NW; i++) { Tcol[i] = (uint16_t)(1u << i); TiRow[i] = (uint16_t)(1u << i); }

    for (int L = 0; L < NLAYERS; L++) {
        int l = L & 1;
        for (int g = 0; g < 4; g++) {
            GroupTab& G = t.grp[L][g];
            int gs = GSIZE[g], w0 = GSTART[g];
            uint16_t v[4] = {0, 0, 0, 0};
            for (int i = 0; i < gs; i++) {
                v[i]       = Tcol[w0 + i];
                G.umask[i] = TiRow[w0 + i];
                G.uidx[i]  = (uint8_t)(l * NW + w0 + i);
            }
            for (int i = gs; i < 4; i++) { G.umask[i] = 0; G.uidx[i] = 0; }
            for (int m = 0; m < (1 << gs); m++) {
                uint16_t o = 0;
                for (int i = 0; i < gs; i++) if ((m >> i) & 1) o = (uint16_t)(o ^ v[i]);
                G.offs[m] = (uint16_t)swz(o);          // pre-swizzled
            }
            for (int m = (1 << gs); m < 16; m++) G.offs[m] = 0;
            uint16_t red[4] = {};
            for (int i = 0; i < 4; i++) red[i] = (i < gs) ? v[i] : (uint16_t)0;
            int piv[4] = {0, 0, 0, 0};
            for (int i = 0; i < gs; i++) {
                int p = 0; while (((red[i] >> p) & 1) == 0) p++;
                piv[i] = p;
                for (int jj = 0; jj < gs; jj++)
                    if (jj != i && ((red[jj] >> p) & 1)) red[jj] = (uint16_t)(red[jj] ^ red[i]);
            }
            for (int a = 0; a < gs; a++)
                for (int b2 = a + 1; b2 < gs; b2++)
                    if (piv[b2] < piv[a]) { int tmp = piv[a]; piv[a] = piv[b2]; piv[b2] = tmp; }
            for (int i = 0; i < gs; i++) G.piv[i] = piv[i];
            for (int i = gs; i < 4; i++) G.piv[i] = 13;
        }
        // CNOT ring layer, range r = (L%2)+1
        int r = l + 1;
        uint16_t Qrow[NW]  = {};
        uint16_t QiRow[NW] = {};
        for (int i = 0; i < NW; i++) { Qrow[i] = (uint16_t)(1u << i); QiRow[i] = (uint16_t)(1u << i); }
        for (int w = NW - 1; w >= 0; w--) Qrow[(w + r) % NW]  = (uint16_t)(Qrow[(w + r) % NW]  ^ Qrow[w]);
        for (int w = 0; w < NW; w++)      QiRow[(w + r) % NW] = (uint16_t)(QiRow[(w + r) % NW] ^ QiRow[w]);
        uint16_t nT[NW]  = {};
        uint16_t nTi[NW] = {};
        for (int w = 0; w < NW; w++) {
            uint16_t c = 0;
            for (int i = 0; i < NW; i++) if ((Qrow[i] >> w) & 1) c = (uint16_t)(c ^ Tcol[i]);
            nT[w] = c;
        }
        for (int i = 0; i < NW; i++) {
            uint16_t rr = 0;
            for (int k = 0; k < NW; k++) if ((QiRow[i] >> k) & 1) rr = (uint16_t)(rr ^ TiRow[k]);
            nTi[i] = rr;
        }
        for (int i = 0; i < NW; i++) { Tcol[i] = nT[i]; TiRow[i] = nTi[i]; }
    }
    for (int i = 0; i < NW; i++) t.zu[i] = TiRow[i];
    return t;
}

__constant__ Tables TAB = build_tables();

// ---------------------------------------------------------------------------
// Packed f32x2 complex helpers. Amplitude packed as u64: lo=re, hi=im.
// Weight w stored as w_rr=(wr,wr) and w_pm=(-wi,wi); then
//   n = fma2(w_rr, a, fma2(w_pm, swap(a), acc))
// yields (wr*ar - wi*ai, wr*ai + wi*ar) lanewise.
// ---------------------------------------------------------------------------
typedef unsigned long long u64;

__device__ __forceinline__ u64 pk(float lo, float hi) {
    u64 r; asm("mov.b64 %0, {%1,%2};" : "=l"(r) : "f"(lo), "f"(hi)); return r;
}
__device__ __forceinline__ u64 sw64(u64 a) {
    unsigned lo, hi;
    asm("mov.b64 {%0,%1}, %2;" : "=r"(lo), "=r"(hi) : "l"(a));
    u64 r; asm("mov.b64 %0, {%1,%2};" : "=l"(r) : "r"(hi), "r"(lo)); return r;
}
__device__ __forceinline__ u64 fma2_(u64 a, u64 b, u64 c) {
    u64 d; asm("fma.rn.f32x2 %0, %1, %2, %3;" : "=l"(d) : "l"(a), "l"(b), "l"(c)); return d;
}
__device__ __forceinline__ u64 mul2_(u64 a, u64 b) {
    u64 d; asm("mul.rn.f32x2 %0, %1, %2;" : "=l"(d) : "l"(a), "l"(b)); return d;
}

#define SGNC 0x8000000080000000ULL

// ---------------------------------------------------------------------------
// Fused multi-gate sweep: each thread owns cosets of 2^G amplitudes,
// applies G commuting Rot gates in registers with packed f32x2 math.
// SU(2) structure ([[u,v],[-conj(v),conj(u)]]) makes the role-swapped
// orientation a pure sign flip in (rr, pm) form -> no selects.
// ---------------------------------------------------------------------------
template <int G>
__device__ __forceinline__ void sweep(u64* __restrict__ st,
                                      const GroupTab& gt,
                                      const u64* __restrict__ Us) {
    u64 urr[G], upm[G], vrr[G], vpm[G];
#pragma unroll
    for (int i = 0; i < G; i++) {
        int base = (int)gt.uidx[i] * 4;
        urr[i] = Us[base + 0];
        upm[i] = Us[base + 1];
        vrr[i] = Us[base + 2];
        vpm[i] = Us[base + 3];
    }
    int piv[G]; unsigned um[G];
#pragma unroll
    for (int i = 0; i < G; i++) { piv[i] = gt.piv[i]; um[i] = gt.umask[i]; }
    unsigned offs[1 << G];
#pragma unroll
    for (int m = 0; m < (1 << G); m++) offs[m] = gt.offs[m];

    const int NG = NSTATE >> G;
    for (int kg = threadIdx.x; kg < NG; kg += NTHREADS) {
        unsigned j = (unsigned)kg;
#pragma unroll
        for (int i = 0; i < G; i++) {                     // insert 0 at pivot bits (ascending)
            unsigned lowmask = (1u << piv[i]) - 1u;
            j = ((j & ~lowmask) << 1) | (j & lowmask);
        }
        unsigned sj = swz(j);
        u64 a[1 << G];
#pragma unroll
        for (int m = 0; m < (1 << G); m++) a[m] = st[sj ^ offs[m]];
#pragma unroll
        for (int i = 0; i < G; i++) {
            u64 bb   = (u64)(__popc(j & um[i]) & 1u);     // logical-role parity of coset rep
            u64 mask = (0ULL - bb) & SGNC;
            u64 A  = urr[i];
            u64 B  = upm[i] ^ mask;                       // w00_pm
            u64 Bn = B ^ SGNC;                            // w11_pm
            u64 C  = vrr[i] ^ mask;                       // w01_rr
            u64 Cn = C ^ SGNC;                            // w10_rr
            u64 D  = vpm[i];                              // w01_pm == w10_pm
#pragma unroll
            for (int m = 0; m < (1 << G); m++) {
                if (m & (1 << i)) continue;
                u64 a0 = a[m], a1 = a[m | (1 << i)];
                u64 a0s = sw64(a0), a1s = sw64(a1);
                a[m]            = fma2_(A, a0, fma2_(B,  a0s, fma2_(C,  a1, mul2_(D, a1s))));
                a[m | (1 << i)] = fma2_(A, a1, fma2_(Bn, a1s, fma2_(Cn, a0, mul2_(D, a0s))));
            }
        }
#pragma unroll
        for (int m = 0; m < (1 << G); m++) st[sj ^ offs[m]] = a[m];
    }
}

__global__ void __launch_bounds__(NTHREADS, 1)
qsim_kernel(const float* __restrict__ state_batch,
            const float* __restrict__ params,
            const float* __restrict__ head_w,
            const float* __restrict__ head_b,
            float* __restrict__ out) {
    extern __shared__ u64 st[];                    // 16384 x 8B = 128 KB
    __shared__ u64   Usm[2 * NW * 4];              // 28 gates x {u_rr,u_pm,v_rr,v_pm}
    __shared__ float redsm[16 * NW];

    const int b   = blockIdx.x;
    const int tid = threadIdx.x;

    // zero state
    for (int i = tid; i < NSTATE; i += NTHREADS) st[i] = 0ULL;

    // 28 distinct Rot matrices (weights shared across the 3 blocks).
    // Rot = [[u, v], [-conj(v), conj(u)]]: u = e^{-i(phi+om)/2} cos(th/2),
    // v = -e^{+i(phi-om)/2} sin(th/2).
    if (tid < 2 * NW) {
        const float* p = params + (size_t)b * NPARAMS + tid * 3;
        float phi = p[0], th = p[1], om = p[2];
        float s, c;  sincosf(0.5f * th, &s, &c);
        float sa, ca; sincosf(0.5f * (phi + om), &sa, &ca);
        float sb, cb; sincosf(0.5f * (phi - om), &sb, &cb);
        float ur =  ca * c, ui = -sa * c;
        float vr = -cb * s, vi = -sb * s;
        u64* U = &Usm[tid * 4];
        U[0] = pk( ur, ur);     // u_rr
        U[1] = pk(-ui, ui);     // u_pm
        U[2] = pk( vr, vr);     // v_rr
        U[3] = pk(-vi, vi);     // v_pm
    }
    __syncthreads();

    // AngleEmbedding: RX(0 or pi) -> basis state (global phase irrelevant)
    if (tid == 0) {
        unsigned j0 = 0;
        const float* sb_ = state_batch + (size_t)b * (NSTATE * 2);
        for (int w = 0; w < NW; w++) if (sb_[w] < 0.f) j0 |= (1u << w);
        st[swz(j0)] = pk(1.f, 0.f);
    }
    __syncthreads();

    // 6 layers: 14 Rots each (fused 4+4+3+3); CNOT layers are free (in TAB)
    for (int L = 0; L < NLAYERS; L++) {
        sweep<4>(st, TAB.grp[L][0], Usm); __syncthreads();
        sweep<4>(st, TAB.grp[L][1], Usm); __syncthreads();
        sweep<3>(st, TAB.grp[L][2], Usm); __syncthreads();
        sweep<3>(st, TAB.grp[L][3], Usm); __syncthreads();
    }

    // <Z_w> via final Tinv sign masks, then linear head
    unsigned zu[NW];
#pragma unroll
    for (int w = 0; w < NW; w++) zu[w] = TAB.zu[w];
    float acc[NW];
#pragma unroll
    for (int w = 0; w < NW; w++) acc[w] = 0.f;
    for (int j = tid; j < NSTATE; j += NTHREADS) {
        u64 av = st[swz((unsigned)j)];
        float ax = __uint_as_float((unsigned)av);
        float ay = __uint_as_float((unsigned)(av >> 32));
        float pv = ax * ax + ay * ay;
        unsigned pb = __float_as_uint(pv);
#pragma unroll
        for (int w = 0; w < NW; w++) {
            unsigned s = (__popc((unsigned)j & zu[w]) & 1u) << 31;
            acc[w] += __uint_as_float(pb ^ s);
        }
    }
#pragma unroll
    for (int w = 0; w < NW; w++) {
#pragma unroll
        for (int o = 16; o > 0; o >>= 1) acc[w] += __shfl_xor_sync(0xffffffffu, acc[w], o);
    }
    const int lane = tid & 31, warp = tid >> 5;
    if (lane == 0) {
#pragma unroll
        for (int w = 0; w < NW; w++) redsm[warp * NW + w] = acc[w];
    }
    __syncthreads();
    if (tid == 0) {
        float r_ = head_b[0];
#pragma unroll
        for (int w = 0; w < NW; w++) {
            float z = 0.f;
            for (int k = 0; k < 16; k++) z += redsm[k * NW + w];
            r_ += z * head_w[w];
        }
        out[b] = r_;
    }
}

extern "C" void kernel_launch(void* const* d_in, const int* in_sizes, int n_in,
                              void* d_out, int out_size) {
    const float* state_batch = (const float*)d_in[0];
    const float* params      = (const float*)d_in[1];
    const float* head_w      = (const float*)d_in[2];
    const float* head_b      = (const float*)d_in[3];
    float* out = (float*)d_out;

    int B = in_sizes[0] / (NSTATE * 2);   // 512
    cudaFuncSetAttribute(qsim_kernel, cudaFuncAttributeMaxDynamicSharedMemorySize,
                         NSTATE * (int)sizeof(u64));
    qsim_kernel<<<B, NTHREADS, NSTATE * sizeof(u64)>>>(state_batch, params, head_w, head_b, out);
}

// round 7
// speedup vs baseline: 1.0146x; 1.0146x over previous
#include <cuda_runtime.h>
#include <cstdint>

#define NW 14
#define NSTATE (1 << NW)        // 16384 amplitudes
#define NLAYERS 6               // (DEPTH+1) * SEL_LAYERS
#define NTHREADS 1024
#define NWARPS (NTHREADS / 32)
#define NPARAMS (2 * NW * 3)    // 84

// ---------------------------------------------------------------------------
// Compile-time GF(2) algebra: lazy CNOT permutation tracking.
// Storage invariant: psi[x] = a[T * x] (T invertible 14x14 over GF(2)).
// Rot on wire w pairs physical (j, j^v), v = col_w(T); role parity =
// <row_w(Tinv), j>.  Linear swizzle sw(j)=j^(j>>4)^(j>>9) folded into offsets.
// All tables are constexpr and specialized per (layer, group) so offsets,
// pivots and parity masks become SASS immediates.
// ---------------------------------------------------------------------------

struct GroupTab {
    int      piv[4];     // sorted pivot bit positions for coset enumeration
    uint16_t offs[16];   // PRE-SWIZZLED xor-offsets of the 2^g coset members
    uint16_t umask[4];   // role-parity masks (rows of Tinv)
    uint8_t  uidx[4];    // index into U-matrix table: l*NW + w
};
struct Tables {
    GroupTab grp[NLAYERS][4];
    uint16_t zu[NW];     // final Tinv rows -> measurement sign masks
};

__host__ __device__ constexpr unsigned swz(unsigned j) {
    return j ^ (j >> 4) ^ (j >> 9);
}

__host__ __device__ constexpr Tables build_tables() {
    Tables t{};
    const int GSIZE[4]  = {4, 4, 3, 3};
    const int GSTART[4] = {0, 4, 8, 11};
    uint16_t Tcol[NW]  = {};
    uint16_t TiRow[NW] = {};
    for (int i = 0; i < NW; i++) { Tcol[i] = (uint16_t)(1u << i); TiRow[i] = (uint16_t)(1u << i); }

    for (int L = 0; L < NLAYERS; L++) {
        int l = L & 1;
        for (int g = 0; g < 4; g++) {
            GroupTab& G = t.grp[L][g];
            int gs = GSIZE[g], w0 = GSTART[g];
            uint16_t v[4] = {0, 0, 0, 0};
            for (int i = 0; i < gs; i++) {
                v[i]       = Tcol[w0 + i];
                G.umask[i] = TiRow[w0 + i];
                G.uidx[i]  = (uint8_t)(l * NW + w0 + i);
            }
            for (int i = gs; i < 4; i++) { G.umask[i] = 0; G.uidx[i] = 0; }
            for (int m = 0; m < (1 << gs); m++) {
                uint16_t o = 0;
                for (int i = 0; i < gs; i++) if ((m >> i) & 1) o = (uint16_t)(o ^ v[i]);
                G.offs[m] = (uint16_t)swz(o);          // pre-swizzled
            }
            for (int m = (1 << gs); m < 16; m++) G.offs[m] = 0;
            uint16_t red[4] = {};
            for (int i = 0; i < 4; i++) red[i] = (i < gs) ? v[i] : (uint16_t)0;
            int piv[4] = {0, 0, 0, 0};
            for (int i = 0; i < gs; i++) {
                int p = 0; while (((red[i] >> p) & 1) == 0) p++;
                piv[i] = p;
                for (int jj = 0; jj < gs; jj++)
                    if (jj != i && ((red[jj] >> p) & 1)) red[jj] = (uint16_t)(red[jj] ^ red[i]);
            }
            for (int a = 0; a < gs; a++)
                for (int b2 = a + 1; b2 < gs; b2++)
                    if (piv[b2] < piv[a]) { int tmp = piv[a]; piv[a] = piv[b2]; piv[b2] = tmp; }
            for (int i = 0; i < gs; i++) G.piv[i] = piv[i];
            for (int i = gs; i < 4; i++) G.piv[i] = 13;
        }
        // CNOT ring layer, range r = (L%2)+1
        int r = l + 1;
        uint16_t Qrow[NW]  = {};
        uint16_t QiRow[NW] = {};
        for (int i = 0; i < NW; i++) { Qrow[i] = (uint16_t)(1u << i); QiRow[i] = (uint16_t)(1u << i); }
        for (int w = NW - 1; w >= 0; w--) Qrow[(w + r) % NW]  = (uint16_t)(Qrow[(w + r) % NW]  ^ Qrow[w]);
        for (int w = 0; w < NW; w++)      QiRow[(w + r) % NW] = (uint16_t)(QiRow[(w + r) % NW] ^ QiRow[w]);
        uint16_t nT[NW]  = {};
        uint16_t nTi[NW] = {};
        for (int w = 0; w < NW; w++) {
            uint16_t c = 0;
            for (int i = 0; i < NW; i++) if ((Qrow[i] >> w) & 1) c = (uint16_t)(c ^ Tcol[i]);
            nT[w] = c;
        }
        for (int i = 0; i < NW; i++) {
            uint16_t rr = 0;
            for (int k = 0; k < NW; k++) if ((QiRow[i] >> k) & 1) rr = (uint16_t)(rr ^ TiRow[k]);
            nTi[i] = rr;
        }
        for (int i = 0; i < NW; i++) { Tcol[i] = nT[i]; TiRow[i] = nTi[i]; }
    }
    for (int i = 0; i < NW; i++) t.zu[i] = TiRow[i];
    return t;
}

// ---------------------------------------------------------------------------
// Packed f32x2 complex helpers. Amplitude packed as u64: lo=re, hi=im.
// Weight w stored as w_rr=(wr,wr) and w_pm=(-wi,wi); then
//   n = fma2(w_rr, a, fma2(w_pm, swap(a), acc))
// yields (wr*ar - wi*ai, wr*ai + wi*ar) lanewise.
// ---------------------------------------------------------------------------
typedef unsigned long long u64;

__device__ __forceinline__ u64 pk(float lo, float hi) {
    u64 r; asm("mov.b64 %0, {%1,%2};" : "=l"(r) : "f"(lo), "f"(hi)); return r;
}
__device__ __forceinline__ u64 sw64(u64 a) {
    unsigned lo, hi;
    asm("mov.b64 {%0,%1}, %2;" : "=r"(lo), "=r"(hi) : "l"(a));
    u64 r; asm("mov.b64 %0, {%1,%2};" : "=l"(r) : "r"(hi), "r"(lo)); return r;
}
__device__ __forceinline__ u64 fma2_(u64 a, u64 b, u64 c) {
    u64 d; asm("fma.rn.f32x2 %0, %1, %2, %3;" : "=l"(d) : "l"(a), "l"(b), "l"(c)); return d;
}
__device__ __forceinline__ u64 mul2_(u64 a, u64 b) {
    u64 d; asm("mul.rn.f32x2 %0, %1, %2;" : "=l"(d) : "l"(a), "l"(b)); return d;
}

#define SGNC 0x8000000080000000ULL

// ---------------------------------------------------------------------------
// Fused multi-gate sweep, constexpr-specialized per (layer, group): all table
// values are immediates. Each thread owns NSTATE>>G / NTHREADS cosets of 2^G
// amplitudes; applies G commuting Rot gates with packed f32x2 math.
// SU(2) structure makes the role-swapped orientation a pure sign flip.
// ---------------------------------------------------------------------------
template <int L, int g, int G>
__device__ __forceinline__ void sweep(u64* __restrict__ st,
                                      const u64* __restrict__ Us) {
    constexpr GroupTab gt = build_tables().grp[L][g];
    constexpr int NITER = (NSTATE >> G) / NTHREADS;

#pragma unroll
    for (int kk = 0; kk < NITER; kk++) {
        unsigned j = threadIdx.x + kk * NTHREADS;
#pragma unroll
        for (int i = 0; i < G; i++) {                     // insert 0 at pivot bits (ascending)
            unsigned lowmask = (1u << gt.piv[i]) - 1u;
            j = ((j & ~lowmask) << 1) | (j & lowmask);
        }
        unsigned sj = swz(j);
        u64 a[1 << G];
#pragma unroll
        for (int m = 0; m < (1 << G); m++) a[m] = st[sj ^ (unsigned)gt.offs[m]];
#pragma unroll
        for (int i = 0; i < G; i++) {
            const u64* Ub = Us + (int)gt.uidx[i] * 4;     // broadcast LDS (no conflicts)
            u64 bb   = (u64)(__popc(j & (unsigned)gt.umask[i]) & 1u);
            u64 mask = (0ULL - bb) & SGNC;
            u64 A  = Ub[0];
            u64 B  = Ub[1] ^ mask;                        // w00_pm
            u64 Bn = B ^ SGNC;                            // w11_pm
            u64 C  = Ub[2] ^ mask;                        // w01_rr
            u64 Cn = C ^ SGNC;                            // w10_rr
            u64 D  = Ub[3];                               // w01_pm == w10_pm
#pragma unroll
            for (int m = 0; m < (1 << G); m++) {
                if (m & (1 << i)) continue;
                u64 a0 = a[m], a1 = a[m | (1 << i)];
                u64 a0s = sw64(a0), a1s = sw64(a1);
                a[m]            = fma2_(A, a0, fma2_(B,  a0s, fma2_(C,  a1, mul2_(D, a1s))));
                a[m | (1 << i)] = fma2_(A, a1, fma2_(Bn, a1s, fma2_(Cn, a0, mul2_(D, a0s))));
            }
        }
#pragma unroll
        for (int m = 0; m < (1 << G); m++) st[sj ^ (unsigned)gt.offs[m]] = a[m];
    }
}

template <int L>
__device__ __forceinline__ void layer(u64* __restrict__ st, const u64* __restrict__ Us) {
    sweep<L, 0, 4>(st, Us); __syncthreads();
    sweep<L, 1, 4>(st, Us); __syncthreads();
    sweep<L, 2, 3>(st, Us); __syncthreads();
    sweep<L, 3, 3>(st, Us); __syncthreads();
}

__global__ void __launch_bounds__(NTHREADS, 1)
qsim_kernel(const float* __restrict__ state_batch,
            const float* __restrict__ params,
            const float* __restrict__ head_w,
            const float* __restrict__ head_b,
            float* __restrict__ out) {
    extern __shared__ u64 st[];                    // 16384 x 8B = 128 KB
    __shared__ u64   Usm[2 * NW * 4];              // 28 gates x {u_rr,u_pm,v_rr,v_pm}
    __shared__ float redsm[NWARPS * NW];

    const int b   = blockIdx.x;
    const int tid = threadIdx.x;

    // zero state
#pragma unroll
    for (int i = tid; i < NSTATE; i += NTHREADS) st[i] = 0ULL;

    // 28 distinct Rot matrices (weights shared across the 3 blocks).
    // Rot = [[u, v], [-conj(v), conj(u)]]: u = e^{-i(phi+om)/2} cos(th/2),
    // v = -e^{+i(phi-om)/2} sin(th/2).
    if (tid < 2 * NW) {
        const float* p = params + (size_t)b * NPARAMS + tid * 3;
        float phi = p[0], th = p[1], om = p[2];
        float s, c;  sincosf(0.5f * th, &s, &c);
        float sa, ca; sincosf(0.5f * (phi + om), &sa, &ca);
        float sb, cb; sincosf(0.5f * (phi - om), &sb, &cb);
        float ur =  ca * c, ui = -sa * c;
        float vr = -cb * s, vi = -sb * s;
        u64* U = &Usm[tid * 4];
        U[0] = pk( ur, ur);     // u_rr
        U[1] = pk(-ui, ui);     // u_pm
        U[2] = pk( vr, vr);     // v_rr
        U[3] = pk(-vi, vi);     // v_pm
    }
    __syncthreads();

    // AngleEmbedding: RX(0 or pi) -> basis state (global phase irrelevant)
    if (tid == 0) {
        unsigned j0 = 0;
        const float* sb_ = state_batch + (size_t)b * (NSTATE * 2);
        for (int w = 0; w < NW; w++) if (sb_[w] < 0.f) j0 |= (1u << w);
        st[swz(j0)] = pk(1.f, 0.f);
    }
    __syncthreads();

    // 6 layers: 14 Rots each (fused 4+4+3+3); CNOT layers are free (constexpr)
    layer<0>(st, Usm);
    layer<1>(st, Usm);
    layer<2>(st, Usm);
    layer<3>(st, Usm);
    layer<4>(st, Usm);
    layer<5>(st, Usm);

    // <Z_w> via final Tinv sign masks, then linear head
    constexpr Tables tt = build_tables();
    float acc[NW];
#pragma unroll
    for (int w = 0; w < NW; w++) acc[w] = 0.f;
#pragma unroll
    for (int kk = 0; kk < NSTATE / NTHREADS; kk++) {
        unsigned j = (unsigned)(tid + kk * NTHREADS);
        u64 av = st[swz(j)];
        float ax = __uint_as_float((unsigned)av);
        float ay = __uint_as_float((unsigned)(av >> 32));
        float pv = ax * ax + ay * ay;
        unsigned pb = __float_as_uint(pv);
#pragma unroll
        for (int w = 0; w < NW; w++) {
            unsigned s = (__popc(j & (unsigned)tt.zu[w]) & 1u) << 31;
            acc[w] += __uint_as_float(pb ^ s);
        }
    }
#pragma unroll
    for (int w = 0; w < NW; w++) {
#pragma unroll
        for (int o = 16; o > 0; o >>= 1) acc[w] += __shfl_xor_sync(0xffffffffu, acc[w], o);
    }
    const int lane = tid & 31, warp = tid >> 5;
    if (lane == 0) {
#pragma unroll
        for (int w = 0; w < NW; w++) redsm[warp * NW + w] = acc[w];
    }
    __syncthreads();
    if (warp == 0 && lane < NW) {
        float z = 0.f;
#pragma unroll
        for (int k = 0; k < NWARPS; k++) z += redsm[k * NW + lane];
        redsm[lane] = z * head_w[lane];
    }
    __syncthreads();
    if (tid == 0) {
        float r_ = head_b[0];
#pragma unroll
        for (int w = 0; w < NW; w++) r_ += redsm[w];
        out[b] = r_;
    }
}

extern "C" void kernel_launch(void* const* d_in, const int* in_sizes, int n_in,
                              void* d_out, int out_size) {
    const float* state_batch = (const float*)d_in[0];
    const float* params      = (const float*)d_in[1];
    const float* head_w      = (const float*)d_in[2];
    const float* head_b      = (const float*)d_in[3];
    float* out = (float*)d_out;

    int B = in_sizes[0] / (NSTATE * 2);   // 512
    cudaFuncSetAttribute(qsim_kernel, cudaFuncAttributeMaxDynamicSharedMemorySize,
                         NSTATE * (int)sizeof(u64));
    qsim_kernel<<<B, NTHREADS, NSTATE * sizeof(u64)>>>(state_batch, params, head_w, head_b, out);
}